// round 2
// baseline (speedup 1.0000x reference)
#include <cuda_runtime.h>
#include <math.h>

#define H    160
#define H3   480
#define CC   200
#define TT   20
#define NCH  10
#define NL   160
#define NCLS 16
#define KS   4
#define HS   40        /* H / KS */
#define RPC  120       /* 3*HS rows per CTA */
#define NT   480
#define NW   15
#define NBLK (NCH + KS*NCH + KS + 1)   /* 10 + 40 + 4 + 1 = 55 */

#define NFLAGS ((NL + 1) * NCH + CC + 4)

/* ---- device scratch (allowed: static device globals) ---- */
__device__ float g_S[(NL + 1) * NCH * H];   /* S[l][t][i]: S[0]=x_cat, S[l+1]=layer-l output */
__device__ float g_hg[CC * H];              /* global GRU hidden per step */
__device__ float g_xl[H];                   /* mean hidden of global GRU */
__device__ int   g_flags[NFLAGS];

#define DONE_IDX(l, t) ((l) * NCH + (t))
#define CNTG_IDX(s)    ((NL + 1) * NCH + (s))
#define GDONE_IDX      ((NL + 1) * NCH + CC)

__device__ __forceinline__ float sigm(float v) { return 1.f / (1.f + expf(-v)); }

__device__ __forceinline__ float warp_red(float a) {
#pragma unroll
    for (int o = 16; o > 0; o >>= 1) a += __shfl_down_sync(0xffffffffu, a, o);
    return a;
}

__device__ __forceinline__ float warp_dot160(const float* __restrict__ wrow,
                                             const float* __restrict__ v, int lane) {
    float a = 0.f;
#pragma unroll
    for (int c = 0; c < 5; ++c) a += wrow[c * 32 + lane] * v[c * 32 + lane];
    return warp_red(a);
}

__device__ __forceinline__ void wait_ge(int idx, int tgt) {
    volatile int* p = (volatile int*)&g_flags[idx];
    while (*p < tgt) {}
}

__global__ void zero_flags_kernel() {
    int i = blockIdx.x * blockDim.x + threadIdx.x;
    if (i < NFLAGS) g_flags[i] = 0;
}

__global__ void __launch_bounds__(NT, 1) spectral_kernel(
    const float* __restrict__ x,
    const float* __restrict__ b_wih, const float* __restrict__ b_whh,
    const float* __restrict__ b_bih, const float* __restrict__ b_bhh,
    const float* __restrict__ gw_ih, const float* __restrict__ gw_hh,
    const float* __restrict__ gb_ih, const float* __restrict__ gb_hh,
    const float* __restrict__ g3_wih, const float* __restrict__ g3_whh,
    const float* __restrict__ g3_bih, const float* __restrict__ g3_bhh,
    const float* __restrict__ bn_gamma, const float* __restrict__ bn_beta,
    const float* __restrict__ bn_mean, const float* __restrict__ bn_var,
    const float* __restrict__ fc_w, const float* __restrict__ fc_b,
    const float* __restrict__ reg_w, const float* __restrict__ reg_b,
    float* __restrict__ out)
{
    extern __shared__ float sm[];
    const int tid  = threadIdx.x;
    const int w    = tid >> 5;
    const int lane = tid & 31;
    const int blk  = blockIdx.x;

    /* ================= ROLE A: branch GRUs (blocks 0..9) ================= */
    if (blk < NCH) {
        const int b = blk;
        float* xp = sm;                 /* [TT*H3] */
        float* h  = sm + TT * H3;       /* [H]     */
        float* hp = h + H;              /* [H3]    */

        const float* wih = b_wih + b * H3;        /* [480,1] */
        const float* bih = b_bih + b * H3;
        const float* whh = b_whh + (size_t)b * H3 * H;
        const float* bhh = b_bhh + b * H3;

        for (int idx = tid; idx < TT * H3; idx += NT) {
            int t = idx / H3, j = idx - t * H3;
            xp[idx] = x[b * TT + t] * wih[j] + bih[j];
        }
        if (tid < H) h[tid] = 0.f;
        __syncthreads();

        for (int t = 0; t < TT; ++t) {
            for (int r = w; r < H3; r += NW) {
                float a = warp_dot160(whh + (size_t)r * H, h, lane);
                if (lane == 0) hp[r] = a + bhh[r];
            }
            __syncthreads();
            if (tid < H) {
                const float* xpt = xp + t * H3;
                float r = sigm(xpt[tid]       + hp[tid]);
                float z = sigm(xpt[H + tid]   + hp[H + tid]);
                float n = tanhf(xpt[2*H + tid] + r * hp[2*H + tid]);
                h[tid] = (1.f - z) * n + z * h[tid];
            }
            __syncthreads();
        }
        if (tid < H) g_S[(0 * NCH + b) * H + tid] = h[tid];
        __threadfence();
        __syncthreads();
        if (tid == 0) atomicExch(&g_flags[DONE_IDX(0, b)], KS);
        return;
    }

    /* ================= ROLE B: g3 wavefront (blocks 10..49) ================= */
    if (blk < NCH + KS * NCH) {
        const int g = blk - NCH;
        const int t = g / KS;
        const int c = g - t * KS;

        float* x_in   = sm;             /* [H]   */
        float* h_prev = sm + H;         /* [H]   */
        float* xps    = sm + 2 * H;     /* [RPC] */
        float* hps    = xps + RPC;      /* [RPC] */

        for (int l = 0; l < NL; ++l) {
            if (tid == 0) {
                wait_ge(DONE_IDX(l, t), KS);                 /* x_in = S[l][t] ready   */
                if (t > 0) wait_ge(DONE_IDX(l + 1, t - 1), KS); /* h_prev = S[l+1][t-1] */
            }
            __syncthreads();
            if (tid < H) {
                x_in[tid]   = g_S[(l * NCH + t) * H + tid];
                h_prev[tid] = (t > 0) ? g_S[((l + 1) * NCH + (t - 1)) * H + tid] : 0.f;
            }
            __syncthreads();

            const float* wih = g3_wih + (size_t)l * H3 * H;
            const float* whh = g3_whh + (size_t)l * H3 * H;
            const float* bih = g3_bih + l * H3;
            const float* bhh = g3_bhh + l * H3;

            for (int q = w; q < RPC; q += NW) {
                int j = (q / HS) * H + c * HS + (q % HS);
                float ax = warp_dot160(wih + (size_t)j * H, x_in,   lane);
                float ah = warp_dot160(whh + (size_t)j * H, h_prev, lane);
                if (lane == 0) { xps[q] = ax + bih[j]; hps[q] = ah + bhh[j]; }
            }
            __syncthreads();

            if (tid < HS) {
                float r = sigm(xps[tid]          + hps[tid]);
                float z = sigm(xps[HS + tid]     + hps[HS + tid]);
                float n = tanhf(xps[2*HS + tid]  + r * hps[2*HS + tid]);
                int i = c * HS + tid;
                float hnew = (1.f - z) * n + z * h_prev[i];
                g_S[((l + 1) * NCH + t) * H + i] = hnew;
            }
            __threadfence();
            __syncthreads();
            if (tid == 0) atomicAdd(&g_flags[DONE_IDX(l + 1, t)], 1);
        }
        return;
    }

    /* ================= ROLE C: global GRU (blocks 50..53) ================= */
    if (blk < NCH + KS * NCH + KS) {
        const int c = blk - (NCH + KS * NCH);

        float* whh_s = sm;                      /* [RPC*H] 76.8 KB */
        float* xp_s  = sm + RPC * H;            /* [CC*RPC] 96 KB  */
        float* bhh_s = xp_s + CC * RPC;         /* [RPC] */
        float* hprev = bhh_s + RPC;             /* [H]   */
        float* hp    = hprev + H;               /* [RPC] */

        for (int idx = tid; idx < RPC * H; idx += NT) {
            int q = idx / H, k = idx - q * H;
            int j = (q / HS) * H + c * HS + (q % HS);
            whh_s[idx] = gw_hh[j * H + k];
        }
        for (int idx = tid; idx < CC * RPC; idx += NT) {
            int s = idx / RPC, q = idx - s * RPC;
            int j = (q / HS) * H + c * HS + (q % HS);
            xp_s[idx] = x[s] * gw_ih[j] + gb_ih[j];
        }
        if (tid < RPC) {
            int q = tid;
            int j = (q / HS) * H + c * HS + (q % HS);
            bhh_s[q] = gb_hh[j];
        }
        __syncthreads();

        float hsum = 0.f;
        for (int s = 0; s < CC; ++s) {
            if (s > 0) {
                if (tid == 0) wait_ge(CNTG_IDX(s - 1), KS);
                __syncthreads();
            }
            if (tid < H) hprev[tid] = (s > 0) ? g_hg[(s - 1) * H + tid] : 0.f;
            __syncthreads();

            for (int q = w; q < RPC; q += NW) {
                float a = 0.f;
#pragma unroll
                for (int c2 = 0; c2 < 5; ++c2)
                    a += whh_s[q * H + c2 * 32 + lane] * hprev[c2 * 32 + lane];
                a = warp_red(a);
                if (lane == 0) hp[q] = a + bhh_s[q];
            }
            __syncthreads();

            if (tid < HS) {
                const float* xpt = xp_s + s * RPC;
                float r = sigm(xpt[tid]         + hp[tid]);
                float z = sigm(xpt[HS + tid]    + hp[HS + tid]);
                float n = tanhf(xpt[2*HS + tid] + r * hp[2*HS + tid]);
                float hnew = (1.f - z) * n + z * hprev[c * HS + tid];
                g_hg[s * H + c * HS + tid] = hnew;
                hsum += hnew;
            }
            __threadfence();
            __syncthreads();
            if (tid == 0) atomicAdd(&g_flags[CNTG_IDX(s)], 1);
        }
        if (tid < HS) g_xl[c * HS + tid] = hsum * (1.f / CC);
        __threadfence();
        __syncthreads();
        if (tid == 0) atomicAdd(&g_flags[GDONE_IDX], 1);
        return;
    }

    /* ================= ROLE D: epilogue (block 54) ================= */
    {
        if (tid == 0) {
            for (int t = 0; t < NCH; ++t) wait_ge(DONE_IDX(NL, t), KS);
            wait_ge(GDONE_IDX, KS);
        }
        __syncthreads();

        float* xr = sm;   /* [H] */
        if (tid < H) {
            float m = 0.f;
            for (int t = 0; t < NCH; ++t) m += g_S[(NL * NCH + t) * H + tid];
            m *= (1.f / NCH);
            m = fmaxf(m, 0.f);                       /* relu(mean) */
            float xnew = g_xl[tid] * m;
            float xb = (xnew - bn_mean[tid]) * rsqrtf(bn_var[tid] + 1e-5f)
                       * bn_gamma[tid] + bn_beta[tid];
            xr[tid] = fmaxf(xb, 0.f);
        }
        __syncthreads();

        for (int r = w; r < NCLS + CC; r += NW) {
            const float* wrow;
            float bias;
            if (r < NCLS) { wrow = fc_w + r * H;            bias = fc_b[r]; }
            else          { wrow = reg_w + (r - NCLS) * H;  bias = reg_b[r - NCLS]; }
            float a = warp_dot160(wrow, xr, lane);
            if (lane == 0) out[r] = a + bias;
        }
        return;
    }
}

extern "C" void kernel_launch(void* const* d_in, const int* in_sizes, int n_in,
                              void* d_out, int out_size) {
    const float* x        = (const float*)d_in[0];
    const float* b_wih    = (const float*)d_in[1];
    const float* b_whh    = (const float*)d_in[2];
    const float* b_bih    = (const float*)d_in[3];
    const float* b_bhh    = (const float*)d_in[4];
    const float* gw_ih    = (const float*)d_in[5];
    const float* gw_hh    = (const float*)d_in[6];
    const float* gb_ih    = (const float*)d_in[7];
    const float* gb_hh    = (const float*)d_in[8];
    const float* g3_wih   = (const float*)d_in[9];
    const float* g3_whh   = (const float*)d_in[10];
    const float* g3_bih   = (const float*)d_in[11];
    const float* g3_bhh   = (const float*)d_in[12];
    const float* bn_gamma = (const float*)d_in[13];
    const float* bn_beta  = (const float*)d_in[14];
    const float* bn_mean  = (const float*)d_in[15];
    const float* bn_var   = (const float*)d_in[16];
    const float* fc_w     = (const float*)d_in[17];
    const float* fc_b     = (const float*)d_in[18];
    const float* reg_w    = (const float*)d_in[19];
    const float* reg_b    = (const float*)d_in[20];
    float* out = (float*)d_out;

    /* global-GRU role smem: (RPC*H + CC*RPC + RPC + H + RPC) floats */
    const int smem_bytes = (RPC * H + CC * RPC + RPC + H + RPC) * (int)sizeof(float);
    cudaFuncSetAttribute(spectral_kernel,
                         cudaFuncAttributeMaxDynamicSharedMemorySize, smem_bytes);

    zero_flags_kernel<<<(NFLAGS + 255) / 256, 256>>>();
    spectral_kernel<<<NBLK, NT, smem_bytes>>>(
        x, b_wih, b_whh, b_bih, b_bhh,
        gw_ih, gw_hh, gb_ih, gb_hh,
        g3_wih, g3_whh, g3_bih, g3_bhh,
        bn_gamma, bn_beta, bn_mean, bn_var,
        fc_w, fc_b, reg_w, reg_b, out);
}

// round 3
// speedup vs baseline: 2.3535x; 2.3535x over previous
#include <cuda_runtime.h>
#include <math.h>
#include <stdint.h>

#define H    160
#define H3   480
#define CC   200
#define TT   20
#define NCH  10
#define NL   160
#define NCLS 16
#define KS   4
#define HS   40
#define RPC  120
#define NT   480
#define NW   15
#define NBLK 56            /* 40 g3 + 4 global + 10 branch + 1 epi + 1 idle */

#define NFLAGS ((NL + 1) * NCH + 1)
#define GDONE_IDX ((NL + 1) * NCH)
#define DONE_IDX(l, t) ((l) * NCH + (t))

/* transposed weights: W_t[l][k][j] */
__device__ float g_wih_t[NL * H * H3];       /* 49.2 MB */
__device__ float g_whh_t[NL * H * H3];       /* 49.2 MB */
__device__ float g_bwhh_t[NCH * H * H3];     /* 3 MB    */
__device__ float g_S[(NL + 1) * NCH * H];    /* wavefront states */
__device__ float g_xl[H];
__device__ int   g_flags[NFLAGS];

__device__ __forceinline__ float sigm(float v) { return 1.f / (1.f + __expf(-v)); }

__device__ __forceinline__ void wait_ge(int idx, int tgt) {
    volatile int* p = (volatile int*)&g_flags[idx];
    while (*p < tgt) {}
}

__device__ __forceinline__ uint32_t smem_u32(const void* p) {
    uint32_t a;
    asm("{ .reg .u64 t; cvta.to.shared.u64 t, %1; cvt.u32.u64 %0, t; }"
        : "=r"(a) : "l"(p));
    return a;
}
__device__ __forceinline__ void st_cluster_f32(uint32_t laddr, int rank, float v) {
    uint32_t r;
    asm("mapa.shared::cluster.u32 %0, %1, %2;" : "=r"(r) : "r"(laddr), "r"(rank));
    asm volatile("st.shared::cluster.f32 [%0], %1;" :: "r"(r), "f"(v) : "memory");
}
#define CLUSTER_SYNC() do { \
    asm volatile("barrier.cluster.arrive.aligned;" ::: "memory"); \
    asm volatile("barrier.cluster.wait.aligned;"   ::: "memory"); } while (0)

__global__ void zero_flags_kernel() {
    int i = blockIdx.x * blockDim.x + threadIdx.x;
    if (i < NFLAGS) g_flags[i] = 0;
}

/* 32x32 tiled transpose: slices 0..159 g3_wih, 160..319 g3_whh, 320..329 b_whh */
__global__ void transpose_kernel(const float* __restrict__ g3_wih,
                                 const float* __restrict__ g3_whh,
                                 const float* __restrict__ b_whh) {
    __shared__ float tile[32][33];
    int slice = blockIdx.z;
    const float* src; float* dst;
    if (slice < NL)            { src = g3_wih + (size_t)slice * H3 * H;        dst = g_wih_t  + (size_t)slice * H * H3; }
    else if (slice < 2 * NL)   { src = g3_whh + (size_t)(slice - NL) * H3 * H; dst = g_whh_t  + (size_t)(slice - NL) * H * H3; }
    else                       { src = b_whh  + (size_t)(slice - 2*NL) * H3 * H; dst = g_bwhh_t + (size_t)(slice - 2*NL) * H * H3; }
    int j0 = blockIdx.x * 32, k0 = blockIdx.y * 32;
    int tx = threadIdx.x, ty = threadIdx.y;
#pragma unroll
    for (int r = ty; r < 32; r += 8)
        tile[r][tx] = src[(size_t)(j0 + r) * H + k0 + tx];
    __syncthreads();
#pragma unroll
    for (int r = ty; r < 32; r += 8)
        dst[(size_t)(k0 + r) * H3 + j0 + tx] = tile[tx][r];
}

__global__ void __launch_bounds__(NT, 1) __cluster_dims__(4, 1, 1)
spectral_kernel(
    const float* __restrict__ x,
    const float* __restrict__ b_wih, const float* __restrict__ b_whh_unused,
    const float* __restrict__ b_bih, const float* __restrict__ b_bhh,
    const float* __restrict__ gw_ih, const float* __restrict__ gw_hh,
    const float* __restrict__ gb_ih, const float* __restrict__ gb_hh,
    const float* __restrict__ g3_bih, const float* __restrict__ g3_bhh,
    const float* __restrict__ bn_gamma, const float* __restrict__ bn_beta,
    const float* __restrict__ bn_mean, const float* __restrict__ bn_var,
    const float* __restrict__ fc_w, const float* __restrict__ fc_b,
    const float* __restrict__ reg_w, const float* __restrict__ reg_b,
    float* __restrict__ out)
{
    extern __shared__ float sm[];
    const int tid = threadIdx.x;
    const int blk = blockIdx.x;

    /* ================= g3 wavefront: blocks 0..39, cluster(4)=time group ===== */
    if (blk < 40) {
        const int t = blk >> 2;
        const int c = blk & 3;

        float* xin2  = sm;              /* [2][H] */
        float* hprev = sm + 2 * H;      /* [H]    */
        float* part  = sm + 3 * H;      /* [NT]   */
        float* xps   = part + NT;       /* [RPC]  */
        float* hps   = xps + RPC;       /* [RPC]  */
        const uint32_t xin_base = smem_u32(xin2);

        const int q_k  = tid / RPC;          /* 0..3  k-quarter */
        const int q    = tid - q_k * RPC;    /* 0..119 row      */
        const int jrow = (q / HS) * H + c * HS + (q % HS);

        /* x_in for l=0: branch t output */
        if (tid == 0) wait_ge(DONE_IDX(0, t), 4);
        __syncthreads();
        if (tid < H) xin2[tid] = __ldcg(&g_S[(0 * NCH + t) * H + tid]);
        __syncthreads();

        for (int l = 0; l < NL; ++l) {
            const int cur = l & 1, nxt = cur ^ 1;

            /* ---- phase X: xp = Wih_t @ x_in (local, no wait) ---- */
            {
                const float* wp = g_wih_t + ((size_t)l * H + q_k * HS) * H3 + jrow;
                const float* xv = xin2 + cur * H + q_k * HS;
                float a0 = 0.f, a1 = 0.f, a2 = 0.f, a3 = 0.f;
#pragma unroll
                for (int i = 0; i < HS; i += 4) {
                    a0 += wp[(i + 0) * H3] * xv[i + 0];
                    a1 += wp[(i + 1) * H3] * xv[i + 1];
                    a2 += wp[(i + 2) * H3] * xv[i + 2];
                    a3 += wp[(i + 3) * H3] * xv[i + 3];
                }
                part[tid] = (a0 + a1) + (a2 + a3);
            }
            __syncthreads();
            if (tid < RPC)
                xps[tid] = part[tid] + part[tid + RPC] + part[tid + 2*RPC] + part[tid + 3*RPC]
                         + __ldcg(&g3_bih[l * H3 + jrow]);
            if (tid == 0 && t > 0) wait_ge(DONE_IDX(l + 1, t - 1), 4);
            __syncthreads();

            /* ---- phase H: hp = Whh_t @ h_prev ---- */
            if (t > 0) {
                if (tid < H) hprev[tid] = __ldcg(&g_S[((l + 1) * NCH + (t - 1)) * H + tid]);
                __syncthreads();
                const float* wp = g_whh_t + ((size_t)l * H + q_k * HS) * H3 + jrow;
                const float* hv = hprev + q_k * HS;
                float a0 = 0.f, a1 = 0.f, a2 = 0.f, a3 = 0.f;
#pragma unroll
                for (int i = 0; i < HS; i += 4) {
                    a0 += wp[(i + 0) * H3] * hv[i + 0];
                    a1 += wp[(i + 1) * H3] * hv[i + 1];
                    a2 += wp[(i + 2) * H3] * hv[i + 2];
                    a3 += wp[(i + 3) * H3] * hv[i + 3];
                }
                part[tid] = (a0 + a1) + (a2 + a3);
                __syncthreads();
                if (tid < RPC)
                    hps[tid] = part[tid] + part[tid + RPC] + part[tid + 2*RPC] + part[tid + 3*RPC]
                             + __ldcg(&g3_bhh[l * H3 + jrow]);
            } else {
                if (tid < RPC) hps[tid] = __ldcg(&g3_bhh[l * H3 + jrow]);
            }
            __syncthreads();

            /* ---- gate + publish ---- */
            if (tid < HS) {
                float r = sigm(xps[tid]          + hps[tid]);
                float z = sigm(xps[HS + tid]     + hps[HS + tid]);
                float n = tanhf(xps[2*HS + tid]  + r * hps[2*HS + tid]);
                float hp_i = (t > 0) ? hprev[c * HS + tid] : 0.f;
                float hn = (1.f - z) * n + z * hp_i;
                uint32_t a = xin_base + (uint32_t)(nxt * H + c * HS + tid) * 4u;
#pragma unroll
                for (int r2 = 0; r2 < 4; ++r2) st_cluster_f32(a, r2, hn);
                g_S[((l + 1) * NCH + t) * H + c * HS + tid] = hn;
            }
            __syncthreads();
            if (tid == 0) { __threadfence(); atomicAdd(&g_flags[DONE_IDX(l + 1, t)], 1); }
            CLUSTER_SYNC();
        }
        return;
    }

    /* ================= global GRU: blocks 40..43, one cluster ================ */
    if (blk < 44) {
        const int c = blk - 40;
        const int PAD = 164;

        float* whh_s = sm;                       /* [RPC*PAD] */
        float* xp_s  = whh_s + RPC * PAD;        /* [CC*RPC]  */
        float* bhh_s = xp_s + CC * RPC;          /* [RPC]     */
        float* h2    = bhh_s + RPC;              /* [2][H]    */
        float* hpb   = h2 + 2 * H;               /* [RPC]     */
        const uint32_t h2_base = smem_u32(h2);

        for (int idx = tid; idx < RPC * H; idx += NT) {
            int q2 = idx / H, k = idx - q2 * H;
            int j = (q2 / HS) * H + c * HS + (q2 % HS);
            whh_s[q2 * PAD + k] = gw_hh[(size_t)j * H + k];
        }
        for (int idx = tid; idx < CC * RPC; idx += NT) {
            int s = idx / RPC, q2 = idx - s * RPC;
            int j = (q2 / HS) * H + c * HS + (q2 % HS);
            xp_s[s * RPC + q2] = x[s] * gw_ih[j] + gb_ih[j];
        }
        if (tid < RPC) {
            int j = (tid / HS) * H + c * HS + (tid % HS);
            bhh_s[tid] = gb_hh[j];
        }
        if (tid < 2 * H) h2[tid] = 0.f;
        __syncthreads();
        CLUSTER_SYNC();

        const int q2  = tid >> 2;      /* row 0..119 */
        const int qk  = tid & 3;       /* k quarter  */
        float hsum = 0.f;

        for (int s = 0; s < CC; ++s) {
            const int cur = s & 1, nxt = cur ^ 1;
            const float* wr = whh_s + q2 * PAD + qk;
            const float* hv = h2 + cur * H + qk;
            float a0 = 0.f, a1 = 0.f;
#pragma unroll
            for (int i = 0; i < HS; i += 2) {
                a0 += wr[(i + 0) * 4] * hv[(i + 0) * 4];
                a1 += wr[(i + 1) * 4] * hv[(i + 1) * 4];
            }
            float a = a0 + a1;
            a += __shfl_xor_sync(0xffffffffu, a, 1);
            a += __shfl_xor_sync(0xffffffffu, a, 2);
            if (qk == 0) hpb[q2] = a + bhh_s[q2];
            __syncthreads();

            if (tid < HS) {
                const float* xpt = xp_s + s * RPC;
                float r = sigm(xpt[tid]          + hpb[tid]);
                float z = sigm(xpt[HS + tid]     + hpb[HS + tid]);
                float n = tanhf(xpt[2*HS + tid]  + r * hpb[2*HS + tid]);
                float hn = (1.f - z) * n + z * h2[cur * H + c * HS + tid];
                hsum += hn;
                uint32_t a2 = h2_base + (uint32_t)(nxt * H + c * HS + tid) * 4u;
#pragma unroll
                for (int r2 = 0; r2 < 4; ++r2) st_cluster_f32(a2, r2, hn);
            }
            CLUSTER_SYNC();
        }
        if (tid < HS) g_xl[c * HS + tid] = hsum * (1.f / CC);
        __syncthreads();
        if (tid == 0) { __threadfence(); atomicAdd(&g_flags[GDONE_IDX], 1); }
        return;
    }

    /* ================= branch GRUs: blocks 44..53 ============================ */
    if (blk < 54) {
        const int b = blk - 44;
        float* xp = sm;                 /* [TT*H3] */
        float* h  = xp + TT * H3;       /* [H]     */
        float* hp = h + H;              /* [H3]    */

        for (int idx = tid; idx < TT * H3; idx += NT) {
            int tt = idx / H3, j = idx - tt * H3;
            xp[idx] = x[b * TT + tt] * b_wih[b * H3 + j] + b_bih[b * H3 + j];
        }
        if (tid < H) h[tid] = 0.f;
        __syncthreads();

        const float* wt = g_bwhh_t + (size_t)b * H * H3 + tid;
        const float  bj = b_bhh[b * H3 + tid];

        for (int tt = 0; tt < TT; ++tt) {
            float a0 = 0.f, a1 = 0.f, a2 = 0.f, a3 = 0.f;
#pragma unroll 10
            for (int k = 0; k < H; k += 4) {
                a0 += wt[(k + 0) * H3] * h[k + 0];
                a1 += wt[(k + 1) * H3] * h[k + 1];
                a2 += wt[(k + 2) * H3] * h[k + 2];
                a3 += wt[(k + 3) * H3] * h[k + 3];
            }
            hp[tid] = (a0 + a1) + (a2 + a3) + bj;
            __syncthreads();
            if (tid < H) {
                const float* xpt = xp + tt * H3;
                float r = sigm(xpt[tid]        + hp[tid]);
                float z = sigm(xpt[H + tid]    + hp[H + tid]);
                float n = tanhf(xpt[2*H + tid] + r * hp[2*H + tid]);
                h[tid] = (1.f - z) * n + z * h[tid];
            }
            __syncthreads();
        }
        if (tid < H) g_S[(0 * NCH + b) * H + tid] = h[tid];
        __syncthreads();
        if (tid == 0) { __threadfence(); atomicAdd(&g_flags[DONE_IDX(0, b)], 4); }
        return;
    }

    /* ================= epilogue: block 54 (55 idle) ========================== */
    if (blk == 54) {
        if (tid == 0) {
            for (int tt = 0; tt < NCH; ++tt) wait_ge(DONE_IDX(NL, tt), 4);
            wait_ge(GDONE_IDX, 4);
        }
        __syncthreads();

        float* xr = sm;
        if (tid < H) {
            float m = 0.f;
#pragma unroll
            for (int tt = 0; tt < NCH; ++tt) m += __ldcg(&g_S[(NL * NCH + tt) * H + tid]);
            m *= (1.f / NCH);
            m = fmaxf(m, 0.f);
            float xnew = __ldcg(&g_xl[tid]) * m;
            float xb = (xnew - bn_mean[tid]) * rsqrtf(bn_var[tid] + 1e-5f)
                       * bn_gamma[tid] + bn_beta[tid];
            xr[tid] = fmaxf(xb, 0.f);
        }
        __syncthreads();

        if (tid < NCLS + CC) {
            const float* wrow; float bias;
            if (tid < NCLS) { wrow = fc_w + tid * H;             bias = fc_b[tid]; }
            else            { wrow = reg_w + (tid - NCLS) * H;   bias = reg_b[tid - NCLS]; }
            float a = bias;
#pragma unroll 10
            for (int k = 0; k < H; ++k) a += wrow[k] * xr[k];
            out[tid] = a;
        }
        return;
    }
}

extern "C" void kernel_launch(void* const* d_in, const int* in_sizes, int n_in,
                              void* d_out, int out_size) {
    const float* x        = (const float*)d_in[0];
    const float* b_wih    = (const float*)d_in[1];
    const float* b_whh    = (const float*)d_in[2];
    const float* b_bih    = (const float*)d_in[3];
    const float* b_bhh    = (const float*)d_in[4];
    const float* gw_ih    = (const float*)d_in[5];
    const float* gw_hh    = (const float*)d_in[6];
    const float* gb_ih    = (const float*)d_in[7];
    const float* gb_hh    = (const float*)d_in[8];
    const float* g3_wih   = (const float*)d_in[9];
    const float* g3_whh   = (const float*)d_in[10];
    const float* g3_bih   = (const float*)d_in[11];
    const float* g3_bhh   = (const float*)d_in[12];
    const float* bn_gamma = (const float*)d_in[13];
    const float* bn_beta  = (const float*)d_in[14];
    const float* bn_mean  = (const float*)d_in[15];
    const float* bn_var   = (const float*)d_in[16];
    const float* fc_w     = (const float*)d_in[17];
    const float* fc_b     = (const float*)d_in[18];
    const float* reg_w    = (const float*)d_in[19];
    const float* reg_b    = (const float*)d_in[20];
    float* out = (float*)d_out;

    const int smem_bytes = (RPC * 164 + CC * RPC + RPC + 2 * H + RPC) * (int)sizeof(float);
    static int configured = 0;
    cudaFuncSetAttribute(spectral_kernel,
                         cudaFuncAttributeMaxDynamicSharedMemorySize, smem_bytes);
    (void)configured;

    zero_flags_kernel<<<(NFLAGS + 255) / 256, 256>>>();
    transpose_kernel<<<dim3(H3 / 32, H / 32, 2 * NL + NCH), dim3(32, 8)>>>(g3_wih, g3_whh, b_whh);
    spectral_kernel<<<NBLK, NT, smem_bytes>>>(
        x, b_wih, b_whh, b_bih, b_bhh,
        gw_ih, gw_hh, gb_ih, gb_hh,
        g3_bih, g3_bhh,
        bn_gamma, bn_beta, bn_mean, bn_var,
        fc_w, fc_b, reg_w, reg_b, out);
}

// round 4
// speedup vs baseline: 3.5039x; 1.4888x over previous
#include <cuda_runtime.h>
#include <math.h>
#include <stdint.h>

#define H    160
#define H3   480
#define CC   200
#define TT   20
#define NCH  10
#define NL   160
#define NCLS 16
#define HS   40
#define RPC  120
#define NT   480
#define NBLK 68

#define NFLAGS ((NL + 1) * NCH + 1)
#define GDONE_IDX ((NL + 1) * NCH)
#define DONE_IDX(l, t) ((l) * NCH + (t))

/* packed weights: g3 wih chunks [0,640), g3 whh chunks [640,1280), branch [1280,1300) */
#define G3_F4   (1280 * 4800)          /* 6,144,000 float4 */
#define BR_F4   (20 * 9600)            /*   192,000 float4 */
#define PACK_F4 (G3_F4 + BR_F4)

__device__ float4 g_pack[PACK_F4];          /* ~101 MB */
__device__ float  g_S[(NL + 1) * NCH * H];
__device__ float  g_xl[H];
__device__ int    g_flags[NFLAGS];

typedef unsigned long long ull;

__device__ __forceinline__ float sigm(float v) { return 1.f / (1.f + __expf(-v)); }

__device__ __forceinline__ void wait_ge(int idx, int tgt) {
    volatile int* p = (volatile int*)&g_flags[idx];
    while (*p < tgt) {}
}

__device__ __forceinline__ uint32_t smem_u32(const void* p) {
    uint32_t a;
    asm("{ .reg .u64 t; cvta.to.shared.u64 t, %1; cvt.u32.u64 %0, t; }"
        : "=r"(a) : "l"(p));
    return a;
}
__device__ __forceinline__ void st_cluster_f32(uint32_t laddr, int rank, float v) {
    uint32_t r;
    asm("mapa.shared::cluster.u32 %0, %1, %2;" : "=r"(r) : "r"(laddr), "r"(rank));
    asm volatile("st.shared::cluster.f32 [%0], %1;" :: "r"(r), "f"(v) : "memory");
}
#define CLUSTER_SYNC() do { \
    asm volatile("barrier.cluster.arrive.aligned;" ::: "memory"); \
    asm volatile("barrier.cluster.wait.aligned;"   ::: "memory"); } while (0)

__device__ __forceinline__ ull pack2(float x, float y) {
    ull u;
    asm("mov.b64 %0, {%1, %2};" : "=l"(u) : "f"(x), "f"(y));
    return u;
}
__device__ __forceinline__ void fma2(ull& acc, ull a, ull b) {
    asm("fma.rn.f32x2 %0, %1, %2, %0;" : "+l"(acc) : "l"(a), "l"(b));
}
__device__ __forceinline__ float upsum(ull a0, ull a1) {
    float l0, h0, l1, h1;
    asm("mov.b64 {%0, %1}, %2;" : "=f"(l0), "=f"(h0) : "l"(a0));
    asm("mov.b64 {%0, %1}, %2;" : "=f"(l1), "=f"(h1) : "l"(a1));
    return (l0 + h0) + (l1 + h1);
}

/* ---------- pack kernel (also zeroes flags) ---------- */
__global__ void pack_kernel(const float4* __restrict__ wih,
                            const float4* __restrict__ whh,
                            const float4* __restrict__ bwhh) {
    int id = blockIdx.x * blockDim.x + threadIdx.x;
    if (id < NFLAGS) g_flags[id] = 0;
    if (id >= PACK_F4) return;
    float4 v;
    if (id < G3_F4) {
        int m      = id / (640 * 4800);
        int rem    = id - m * (640 * 4800);
        int chunk  = rem / 4800;                  /* l*4 + c */
        int within = rem - chunk * 4800;
        int i4 = within / 480, tid = within - i4 * 480;
        int l = chunk >> 2, c = chunk & 3;
        int q = tid >> 2, qk = tid & 3;
        int jrow = (q / HS) * H + c * HS + (q % HS);
        int k4 = qk * 10 + i4;
        const float4* src = (m == 0) ? wih : whh;
        v = src[((size_t)l * H3 + jrow) * 40 + k4];
    } else {
        int id2    = id - G3_F4;
        int chunk  = id2 / 9600;                  /* b*2 + hh */
        int within = id2 - chunk * 9600;
        int i4 = within / 480, tid = within - i4 * 480;
        int b = chunk >> 1, hh = chunk & 1;
        int qk2 = tid & 1, gi = tid >> 1;
        int g = gi / 80, ip = gi - g * 80;
        int j = g * H + hh * 80 + ip;
        int k4 = qk2 * 20 + i4;
        v = bwhh[((size_t)b * H3 + j) * 40 + k4];
    }
    g_pack[id] = v;
}

/* ---------- main persistent kernel ---------- */
__global__ void __launch_bounds__(NT, 1) __cluster_dims__(4, 1, 1)
spectral_kernel(
    const float* __restrict__ x,
    const float* __restrict__ b_wih, const float* __restrict__ b_bih,
    const float* __restrict__ b_bhh,
    const float* __restrict__ gw_ih, const float* __restrict__ gw_hh,
    const float* __restrict__ gb_ih, const float* __restrict__ gb_hh,
    const float* __restrict__ g3_bih, const float* __restrict__ g3_bhh,
    const float* __restrict__ bn_gamma, const float* __restrict__ bn_beta,
    const float* __restrict__ bn_mean, const float* __restrict__ bn_var,
    const float* __restrict__ fc_w, const float* __restrict__ fc_b,
    const float* __restrict__ reg_w, const float* __restrict__ reg_b,
    float* __restrict__ out)
{
    extern __shared__ float sm[];
    const int tid = threadIdx.x;
    const int blk = blockIdx.x;
    const float4* packW = g_pack;

    /* ============ g3 wavefront: blocks 0..39 (cluster = time group) ======== */
    if (blk < 40) {
        const int t = blk >> 2;
        const int c = blk & 3;
        const int q  = tid >> 2;           /* row 0..119 */
        const int qk = tid & 3;            /* k-quarter  */
        const int jrow = (q / HS) * H + c * HS + (q % HS);

        float* xin2  = sm;                 /* [2][H]  */
        float* hprev = sm + 2 * H;         /* [H]     */
        float* xps   = sm + 3 * H;         /* [RPC]   */
        float* hps   = xps + RPC;          /* [RPC]   */
        const uint32_t xin_base = smem_u32(xin2);

        ull Wx[20], Wh[20];
        /* preload wih(0) */
        {
            size_t base = (size_t)(0 * 4 + c) * 4800 + tid;
#pragma unroll
            for (int i4 = 0; i4 < 10; ++i4) {
                float4 f = __ldg(&packW[base + i4 * 480]);
                Wx[2 * i4] = pack2(f.x, f.y); Wx[2 * i4 + 1] = pack2(f.z, f.w);
            }
        }
        if (tid == 0) wait_ge(DONE_IDX(0, t), 4);
        __syncthreads();
        if (tid < 40)
            *(float4*)&xin2[tid * 4] = __ldcg((const float4*)&g_S[(0 * NCH + t) * H + tid * 4]);
        __syncthreads();

        for (int l = 0; l < NL; ++l) {
            const int cur = l & 1, nxt = cur ^ 1;
            float bih_v = 0.f, bhh_v = 0.f;
            if (qk == 0) { bih_v = g3_bih[l * H3 + jrow]; bhh_v = g3_bhh[l * H3 + jrow]; }

            /* preload whh(l) — consumed after the wait */
            {
                size_t base = (size_t)(640 + l * 4 + c) * 4800 + tid;
#pragma unroll
                for (int i4 = 0; i4 < 10; ++i4) {
                    float4 f = __ldg(&packW[base + i4 * 480]);
                    Wh[2 * i4] = pack2(f.x, f.y); Wh[2 * i4 + 1] = pack2(f.z, f.w);
                }
            }

            /* phase X */
            {
                const float* xv = xin2 + cur * H + qk * HS;
                ull a0 = 0, a1 = 0;
#pragma unroll
                for (int i4 = 0; i4 < 10; ++i4) {
                    ulonglong2 hv = *(const ulonglong2*)(xv + i4 * 4);
                    fma2(a0, Wx[2 * i4], hv.x);
                    fma2(a1, Wx[2 * i4 + 1], hv.y);
                }
                float a = upsum(a0, a1);
                a += __shfl_xor_sync(0xffffffffu, a, 1);
                a += __shfl_xor_sync(0xffffffffu, a, 2);
                if (qk == 0) xps[q] = a + bih_v;
            }

            /* preload wih(l+1) — consumed next iter */
            if (l + 1 < NL) {
                size_t base = (size_t)((l + 1) * 4 + c) * 4800 + tid;
#pragma unroll
                for (int i4 = 0; i4 < 10; ++i4) {
                    float4 f = __ldg(&packW[base + i4 * 480]);
                    Wx[2 * i4] = pack2(f.x, f.y); Wx[2 * i4 + 1] = pack2(f.z, f.w);
                }
            }

            /* phase H */
            if (t > 0) {
                if (tid == 0) wait_ge(DONE_IDX(l + 1, t - 1), 4);
                __syncthreads();
                if (tid < 40)
                    *(float4*)&hprev[tid * 4] =
                        __ldcg((const float4*)&g_S[((l + 1) * NCH + (t - 1)) * H + tid * 4]);
                __syncthreads();
                const float* hv0 = hprev + qk * HS;
                ull a0 = 0, a1 = 0;
#pragma unroll
                for (int i4 = 0; i4 < 10; ++i4) {
                    ulonglong2 hv = *(const ulonglong2*)(hv0 + i4 * 4);
                    fma2(a0, Wh[2 * i4], hv.x);
                    fma2(a1, Wh[2 * i4 + 1], hv.y);
                }
                float a = upsum(a0, a1);
                a += __shfl_xor_sync(0xffffffffu, a, 1);
                a += __shfl_xor_sync(0xffffffffu, a, 2);
                if (qk == 0) hps[q] = a + bhh_v;
            } else {
                if (qk == 0) hps[q] = bhh_v;
            }
            __syncthreads();

            /* gate + publish */
            if (tid < 160 && (tid & 3) == 0) {
                int i = tid >> 2;
                float r = sigm(xps[i]        + hps[i]);
                float z = sigm(xps[40 + i]   + hps[40 + i]);
                float n = tanhf(xps[80 + i]  + r * hps[80 + i]);
                float hp_i = (t > 0) ? hprev[c * HS + i] : 0.f;
                float hn = (1.f - z) * n + z * hp_i;
                uint32_t a3 = xin_base + (uint32_t)(nxt * H + c * HS + i) * 4u;
#pragma unroll
                for (int r2 = 0; r2 < 4; ++r2) st_cluster_f32(a3, r2, hn);
                g_S[((l + 1) * NCH + t) * H + c * HS + i] = hn;
            }
            __syncthreads();
            if (tid == 0) { __threadfence(); atomicAdd(&g_flags[DONE_IDX(l + 1, t)], 1); }
            CLUSTER_SYNC();
        }
        return;
    }

    /* ============ global GRU: blocks 40..43, one cluster (as R2) =========== */
    if (blk < 44) {
        const int c = blk - 40;
        const int PAD = 164;

        float* whh_s = sm;                       /* [RPC*PAD] */
        float* xp_s  = whh_s + RPC * PAD;        /* [CC*RPC]  */
        float* bhh_s = xp_s + CC * RPC;          /* [RPC]     */
        float* h2    = bhh_s + RPC;              /* [2][H]    */
        float* hpb   = h2 + 2 * H;               /* [RPC]     */
        const uint32_t h2_base = smem_u32(h2);

        for (int idx = tid; idx < RPC * H; idx += NT) {
            int q2 = idx / H, k = idx - q2 * H;
            int j = (q2 / HS) * H + c * HS + (q2 % HS);
            whh_s[q2 * PAD + k] = gw_hh[(size_t)j * H + k];
        }
        for (int idx = tid; idx < CC * RPC; idx += NT) {
            int s = idx / RPC, q2 = idx - s * RPC;
            int j = (q2 / HS) * H + c * HS + (q2 % HS);
            xp_s[s * RPC + q2] = x[s] * gw_ih[j] + gb_ih[j];
        }
        if (tid < RPC) {
            int j = (tid / HS) * H + c * HS + (tid % HS);
            bhh_s[tid] = gb_hh[j];
        }
        if (tid < 2 * H) h2[tid] = 0.f;
        __syncthreads();
        CLUSTER_SYNC();

        const int q2 = tid >> 2;
        const int qk = tid & 3;
        float hsum = 0.f;

        for (int s = 0; s < CC; ++s) {
            const int cur = s & 1, nxt = cur ^ 1;
            const float* wr = whh_s + q2 * PAD + qk;
            const float* hv = h2 + cur * H + qk;
            float a0 = 0.f, a1 = 0.f;
#pragma unroll
            for (int i = 0; i < HS; i += 2) {
                a0 += wr[(i + 0) * 4] * hv[(i + 0) * 4];
                a1 += wr[(i + 1) * 4] * hv[(i + 1) * 4];
            }
            float a = a0 + a1;
            a += __shfl_xor_sync(0xffffffffu, a, 1);
            a += __shfl_xor_sync(0xffffffffu, a, 2);
            if (qk == 0) hpb[q2] = a + bhh_s[q2];
            __syncthreads();

            if (tid < HS) {
                const float* xpt = xp_s + s * RPC;
                float r = sigm(xpt[tid]          + hpb[tid]);
                float z = sigm(xpt[HS + tid]     + hpb[HS + tid]);
                float n = tanhf(xpt[2*HS + tid]  + r * hpb[2*HS + tid]);
                float hn = (1.f - z) * n + z * h2[cur * H + c * HS + tid];
                hsum += hn;
                uint32_t a2 = h2_base + (uint32_t)(nxt * H + c * HS + tid) * 4u;
#pragma unroll
                for (int r2 = 0; r2 < 4; ++r2) st_cluster_f32(a2, r2, hn);
            }
            CLUSTER_SYNC();
        }
        if (tid < HS) g_xl[c * HS + tid] = hsum * (1.f / CC);
        __syncthreads();
        if (tid == 0) { __threadfence(); atomicAdd(&g_flags[GDONE_IDX], 1); }
        return;
    }

    /* ============ branch GRUs: blocks 44..63 (2 CTAs per branch) =========== */
    if (blk < 64) {
        const int pairblk = blk - 44;
        const int b  = pairblk >> 1;
        const int hh = pairblk & 1;
        const int rank = pairblk & 3;          /* cluster rank */

        float* xp_s = sm;                      /* [TT*240]  */
        float* h2   = sm + TT * 240;           /* [2][H]    */
        float* hp_s = h2 + 2 * H;              /* [240]     */
        const uint32_t h2b = smem_u32(h2);

        const int qk2 = tid & 1;
        const int gi  = tid >> 1;
        const int g   = gi / 80;
        const int ip  = gi - g * 80;
        const int jrow = g * H + hh * 80 + ip;

        ull W[40];
        {
            size_t base = (size_t)G3_F4 + (size_t)(b * 2 + hh) * 9600 + tid;
#pragma unroll
            for (int i4 = 0; i4 < 20; ++i4) {
                float4 f = __ldg(&packW[base + i4 * 480]);
                W[2 * i4] = pack2(f.x, f.y); W[2 * i4 + 1] = pack2(f.z, f.w);
            }
        }
        float bhh_v = 0.f;
        if (qk2 == 0) bhh_v = b_bhh[b * H3 + jrow];

        for (int idx = tid; idx < TT * 240; idx += NT) {
            int tt = idx / 240, lr = idx - tt * 240;
            int j = (lr / 80) * H + hh * 80 + (lr % 80);
            xp_s[idx] = x[b * TT + tt] * b_wih[b * H3 + j] + b_bih[b * H3 + j];
        }
        if (tid < 2 * H) h2[tid] = 0.f;
        __syncthreads();
        CLUSTER_SYNC();

        for (int tt = 0; tt < TT; ++tt) {
            const int cur = tt & 1, nxt = cur ^ 1;
            const float* hv0 = h2 + cur * H + qk2 * 80;
            ull a0 = 0, a1 = 0;
#pragma unroll
            for (int i4 = 0; i4 < 20; ++i4) {
                ulonglong2 hv = *(const ulonglong2*)(hv0 + i4 * 4);
                fma2(a0, W[2 * i4], hv.x);
                fma2(a1, W[2 * i4 + 1], hv.y);
            }
            float a = upsum(a0, a1);
            a += __shfl_xor_sync(0xffffffffu, a, 1);
            if (qk2 == 0) hp_s[g * 80 + ip] = a + bhh_v;
            __syncthreads();

            if (tid < 80) {
                const float* xpt = xp_s + tt * 240;
                float r = sigm(xpt[tid]        + hp_s[tid]);
                float z = sigm(xpt[80 + tid]   + hp_s[80 + tid]);
                float n = tanhf(xpt[160 + tid] + r * hp_s[160 + tid]);
                float hn = (1.f - z) * n + z * h2[cur * H + hh * 80 + tid];
                uint32_t a3 = h2b + (uint32_t)(nxt * H + hh * 80 + tid) * 4u;
                st_cluster_f32(a3, rank, hn);
                st_cluster_f32(a3, rank ^ 1, hn);
            }
            CLUSTER_SYNC();
        }
        /* final h is in h2[TT&1 ? ... ] : after tt=19 (cur=1) stored to nxt=0 */
        if (tid < 80) g_S[(0 * NCH + b) * H + hh * 80 + tid] = h2[0 * H + hh * 80 + tid];
        __syncthreads();
        if (tid == 0) { __threadfence(); atomicAdd(&g_flags[DONE_IDX(0, b)], 2); }
        return;
    }

    /* ============ epilogue: block 64 (65..67 idle) ========================= */
    if (blk == 64) {
        if (tid == 0) {
            for (int tt = 0; tt < NCH; ++tt) wait_ge(DONE_IDX(NL, tt), 4);
            wait_ge(GDONE_IDX, 4);
        }
        __syncthreads();

        float* xr = sm;
        if (tid < H) {
            float m = 0.f;
#pragma unroll
            for (int tt = 0; tt < NCH; ++tt) m += __ldcg(&g_S[(NL * NCH + tt) * H + tid]);
            m *= (1.f / NCH);
            m = fmaxf(m, 0.f);
            float xnew = __ldcg(&g_xl[tid]) * m;
            float xb = (xnew - bn_mean[tid]) * rsqrtf(bn_var[tid] + 1e-5f)
                       * bn_gamma[tid] + bn_beta[tid];
            xr[tid] = fmaxf(xb, 0.f);
        }
        __syncthreads();

        if (tid < NCLS + CC) {
            const float* wrow; float bias;
            if (tid < NCLS) { wrow = fc_w + tid * H;           bias = fc_b[tid]; }
            else            { wrow = reg_w + (tid - NCLS) * H; bias = reg_b[tid - NCLS]; }
            float a = bias;
#pragma unroll 10
            for (int k = 0; k < H; ++k) a += wrow[k] * xr[k];
            out[tid] = a;
        }
        return;
    }
}

extern "C" void kernel_launch(void* const* d_in, const int* in_sizes, int n_in,
                              void* d_out, int out_size) {
    const float* x        = (const float*)d_in[0];
    const float* b_wih    = (const float*)d_in[1];
    const float* b_whh    = (const float*)d_in[2];
    const float* b_bih    = (const float*)d_in[3];
    const float* b_bhh    = (const float*)d_in[4];
    const float* gw_ih    = (const float*)d_in[5];
    const float* gw_hh    = (const float*)d_in[6];
    const float* gb_ih    = (const float*)d_in[7];
    const float* gb_hh    = (const float*)d_in[8];
    const float* g3_wih   = (const float*)d_in[9];
    const float* g3_whh   = (const float*)d_in[10];
    const float* g3_bih   = (const float*)d_in[11];
    const float* g3_bhh   = (const float*)d_in[12];
    const float* bn_gamma = (const float*)d_in[13];
    const float* bn_beta  = (const float*)d_in[14];
    const float* bn_mean  = (const float*)d_in[15];
    const float* bn_var   = (const float*)d_in[16];
    const float* fc_w     = (const float*)d_in[17];
    const float* fc_b     = (const float*)d_in[18];
    const float* reg_w    = (const float*)d_in[19];
    const float* reg_b    = (const float*)d_in[20];
    float* out = (float*)d_out;

    const int smem_bytes = (RPC * 164 + CC * RPC + RPC + 2 * H + RPC) * (int)sizeof(float);
    cudaFuncSetAttribute(spectral_kernel,
                         cudaFuncAttributeMaxDynamicSharedMemorySize, smem_bytes);

    pack_kernel<<<(PACK_F4 + 255) / 256, 256>>>(
        (const float4*)g3_wih, (const float4*)g3_whh, (const float4*)b_whh);
    spectral_kernel<<<NBLK, NT, smem_bytes>>>(
        x, b_wih, b_bih, b_bhh,
        gw_ih, gw_hh, gb_ih, gb_hh,
        g3_bih, g3_bhh,
        bn_gamma, bn_beta, bn_mean, bn_var,
        fc_w, fc_b, reg_w, reg_b, out);
}